// round 16
// baseline (speedup 1.0000x reference)
#include <cuda_runtime.h>
#include <cuda_fp16.h>
#include <cstdint>

// B=4, T=2048, E=768, H=64 — causal single-head attention, fp32 out.
//  K1 qkv_gemm_mma: tf32 m16n8k8 GEMM (R13 config), Q-scale*log2e folded.
//  K2 attn_kernel: fp16 flash attention, BQ=128, PROPORTIONAL split-K
//     (tile t gets ceil((t+1)/2) chunks -> every CTA <= 4 visits),
//     ex2 softmax, fused last-CTA combine.

#define BATCH 4
#define SEQ   2048
#define EMB   768
#define HDIM  64
#define ROWS  (BATCH*SEQ)   // 8192
#define MAXCH 8             // max chunks per tile (tile 15)
#define CTAS_PER_B 72       // sum of ceil((t+1)/2), t=0..15
#define LOG2E 1.4426950408889634f

__device__ __half g_qh[ROWS*HDIM], g_kh[ROWS*HDIM], g_vh[ROWS*HDIM];
__device__ float g_pm[MAXCH][ROWS], g_pl[MAXCH][ROWS], g_po[MAXCH][ROWS*HDIM];
__device__ int   g_cnt[64];                                       // [b][tile]

// ---------------- helpers (sm_80+ baseline PTX) ------------------------------
__device__ __forceinline__ void ldsm_x4(uint32_t* r, const void* p) {
    uint32_t a = (uint32_t)__cvta_generic_to_shared(p);
    asm volatile("ldmatrix.sync.aligned.m8n8.x4.shared.b16 {%0,%1,%2,%3}, [%4];"
                 : "=r"(r[0]), "=r"(r[1]), "=r"(r[2]), "=r"(r[3]) : "r"(a));
}
__device__ __forceinline__ void ldsm_x4_t(uint32_t* r, const void* p) {
    uint32_t a = (uint32_t)__cvta_generic_to_shared(p);
    asm volatile("ldmatrix.sync.aligned.m8n8.x4.trans.shared.b16 {%0,%1,%2,%3}, [%4];"
                 : "=r"(r[0]), "=r"(r[1]), "=r"(r[2]), "=r"(r[3]) : "r"(a));
}
__device__ __forceinline__ void mma16816(float* c, const uint32_t* a,
                                         uint32_t b0, uint32_t b1) {
    asm volatile("mma.sync.aligned.m16n8k16.row.col.f32.f16.f16.f32 "
                 "{%0,%1,%2,%3}, {%4,%5,%6,%7}, {%8,%9}, {%0,%1,%2,%3};"
                 : "+f"(c[0]), "+f"(c[1]), "+f"(c[2]), "+f"(c[3])
                 : "r"(a[0]), "r"(a[1]), "r"(a[2]), "r"(a[3]), "r"(b0), "r"(b1));
}
__device__ __forceinline__ void mma16888(float* c,
                                         uint32_t a0, uint32_t a1, uint32_t a2, uint32_t a3,
                                         uint32_t b0, uint32_t b1) {
    asm volatile("mma.sync.aligned.m16n8k8.row.col.f32.tf32.tf32.f32 "
                 "{%0,%1,%2,%3}, {%4,%5,%6,%7}, {%8,%9}, {%0,%1,%2,%3};"
                 : "+f"(c[0]), "+f"(c[1]), "+f"(c[2]), "+f"(c[3])
                 : "r"(a0), "r"(a1), "r"(a2), "r"(a3), "r"(b0), "r"(b1));
}
__device__ __forceinline__ uint32_t cvt_tf32(float s) {
    uint32_t d;
    asm("cvt.rna.tf32.f32 %0, %1;" : "=r"(d) : "f"(s));
    return d;
}
__device__ __forceinline__ float ex2(float x) {
    float y;
    asm("ex2.approx.f32 %0, %1;" : "=f"(y) : "f"(x));
    return y;
}
__device__ __forceinline__ uint32_t packh2(float a, float b) {
    __half2 h = __floats2half2_rn(a, b);
    return *reinterpret_cast<uint32_t*>(&h);
}
__device__ __forceinline__ void cp16(void* dst, const void* src) {
    uint32_t d = (uint32_t)__cvta_generic_to_shared(dst);
    asm volatile("cp.async.cg.shared.global [%0], [%1], 16;" :: "r"(d), "l"(src));
}

extern __shared__ char smbase[];

#define NEG_BIG (-1e30f)
#define MFLOOR  (-1e28f)

// ---------------------------------------------------------------------------
// K1: fused QKV GEMM on tf32 (unchanged from R15). CTA = 64x192, 8 warps,
// warp tile 32x48 via m16n8k8, BKC=96, 2-stage cp.async.
// ---------------------------------------------------------------------------
#define BM    64
#define BKC   96
#define XSTRF 100
#define WSTR  200
#define STGB  (BM*XSTRF*4 + BKC*WSTR*4)   // 102400

__device__ __forceinline__ void gemm_load_stage(char* st, const float* x,
                                                const float* Wq, const float* Wk,
                                                const float* Wv, int m0, int kc0, int t)
{
    float* Xf = (float*)st;
    float* Wf = (float*)(st + BM * XSTRF * 4);

    {
        int row = t >> 2, coff = (t & 3) * 24;
        const float* sx = x + (size_t)(m0 + row) * EMB + kc0 + coff;
        #pragma unroll
        for (int i = 0; i < 6; i++)
            cp16(&Xf[row * XSTRF + coff + i * 4], sx + i * 4);
    }
    #pragma unroll
    for (int i = 0; i < 18; i++) {
        int idx = t + i * 256;
        int wr = idx / 48, c = idx % 48;
        const float* Warr = (c < 16) ? Wq : (c < 32) ? Wk : Wv;
        int wc = (c & 15) * 4;
        cp16(&Wf[wr * WSTR + c * 4], Warr + (size_t)(kc0 + wr) * HDIM + wc);
    }
}

__global__ __launch_bounds__(256)
void qkv_gemm_mma(const float* __restrict__ x,
                  const float* __restrict__ Wk,
                  const float* __restrict__ Wq,
                  const float* __restrict__ Wv)
{
    if (blockIdx.x == 0 && threadIdx.x < 64) g_cnt[threadIdx.x] = 0;

    const int m0   = blockIdx.x * BM;
    const int t    = threadIdx.x;
    const int w    = t >> 5;
    const int lane = t & 31;
    const int rg   = w >> 2;
    const int cg   = w & 3;
    const int gid  = lane >> 2;
    const int tid  = lane & 3;

    const float qsc = rsqrtf((float)EMB) * LOG2E;

    float c[2][6][4];
    #pragma unroll
    for (int mt = 0; mt < 2; mt++)
        #pragma unroll
        for (int j = 0; j < 6; j++)
            #pragma unroll
            for (int e = 0; e < 4; e++) c[mt][j][e] = 0.f;

    const int NC = EMB / BKC;   // 8

    gemm_load_stage(smbase, x, Wq, Wk, Wv, m0, 0, t);
    asm volatile("cp.async.commit_group;");

    for (int kc = 0; kc < NC; kc++) {
        if (kc + 1 < NC) {
            gemm_load_stage(smbase + ((kc + 1) & 1) * STGB, x, Wq, Wk, Wv,
                            m0, (kc + 1) * BKC, t);
            asm volatile("cp.async.commit_group;");
            asm volatile("cp.async.wait_group 1;");
        } else {
            asm volatile("cp.async.wait_group 0;");
        }
        __syncthreads();

        char*  st = smbase + (kc & 1) * STGB;
        float* Xf = (float*)st;
        float* Wf = (float*)(st + BM * XSTRF * 4);

        #pragma unroll
        for (int kt = 0; kt < BKC / 8; kt++) {
            uint32_t a[2][4];
            #pragma unroll
            for (int mt = 0; mt < 2; mt++) {
                const float* ab = &Xf[(rg * 32 + mt * 16 + gid) * XSTRF + kt * 8 + tid];
                a[mt][0] = cvt_tf32(ab[0]);
                a[mt][1] = cvt_tf32(ab[8 * XSTRF]);
                a[mt][2] = cvt_tf32(ab[4]);
                a[mt][3] = cvt_tf32(ab[8 * XSTRF + 4]);
            }
            #pragma unroll
            for (int nt = 0; nt < 6; nt++) {
                const float sc = (cg * 48 + nt * 8 < 64) ? qsc : 1.0f;
                const float* bb = &Wf[(kt * 8 + tid) * WSTR + cg * 48 + nt * 8 + gid];
                uint32_t b0 = cvt_tf32(bb[0] * sc);
                uint32_t b1 = cvt_tf32(bb[4 * WSTR] * sc);
                mma16888(c[0][nt], a[0][0], a[0][1], a[0][2], a[0][3], b0, b1);
                mma16888(c[1][nt], a[1][0], a[1][1], a[1][2], a[1][3], b0, b1);
            }
        }
        __syncthreads();
    }

    #pragma unroll
    for (int mt = 0; mt < 2; mt++) {
        int r0 = m0 + rg * 32 + mt * 16 + gid;
        #pragma unroll
        for (int j = 0; j < 6; j++) {
            int col_local = cg * 48 + j * 8 + 2 * tid;
            int widx = col_local >> 6;
            int col  = col_local & 63;
            __half* oh = (widx == 0) ? g_qh : (widx == 1) ? g_kh : g_vh;
            *(uint32_t*)&oh[(size_t)r0 * HDIM + col]       = packh2(c[mt][j][0], c[mt][j][1]);
            *(uint32_t*)&oh[(size_t)(r0 + 8) * HDIM + col] = packh2(c[mt][j][2], c[mt][j][3]);
        }
    }
}

// ---------------------------------------------------------------------------
// K2: fp16 flash attention, proportional split-K. Tile t (0..15) gets
// ct = (t+2)>>1 chunks; chunk handles kb = chunk, chunk+ct, ... (<= 4 visits).
// cp.async double-buffered K/V; ex2 softmax; fused last-CTA combine (ct-aware).
// smem: sQ[128*72] + stages[2][K,V][64*72] halves = 55296 B dynamic.
// ---------------------------------------------------------------------------
#define BQ   128
#define BK   64
#define STR  72

__device__ __forceinline__ void attn_load_kv(__half* Kh, __half* Vh,
                                             int b, int k0, int t)
{
    int row = t >> 2, off = (t & 3) * 16;
    const __half* sk = g_kh + (size_t)(b * SEQ + k0 + row) * HDIM + off;
    const __half* sv = g_vh + (size_t)(b * SEQ + k0 + row) * HDIM + off;
    cp16(&Kh[row * STR + off],     sk);
    cp16(&Kh[row * STR + off + 8], sk + 8);
    cp16(&Vh[row * STR + off],     sv);
    cp16(&Vh[row * STR + off + 8], sv + 8);
}

__global__ __launch_bounds__(256, 2)
void attn_kernel(float* __restrict__ out)
{
    __half* sQ = (__half*)smbase;                     // 9216 halves
    __half* sKV[2][2];
    #pragma unroll
    for (int s = 0; s < 2; s++)
        #pragma unroll
        for (int kv = 0; kv < 2; kv++)
            sKV[s][kv] = (__half*)smbase + BQ * STR + (s * 2 + kv) * BK * STR;

    __shared__ int s_last;

    const int b = blockIdx.y;
    // ---- proportional (tile, chunk) from blockIdx.x ----
    int tile = 0, chunk = 0;
    {
        int bid = blockIdx.x, acc = 0;
        #pragma unroll
        for (int tt = 0; tt < 16; tt++) {
            int c16 = (tt + 2) >> 1;
            if (bid < acc + c16) { tile = tt; chunk = bid - acc; break; }
            acc += c16;
        }
    }
    const int ct  = (tile + 2) >> 1;     // chunks for this tile (stride)
    const int q0  = tile * BQ;
    const int nkb = 2 * tile + 2;

    const int t    = threadIdx.x;
    const int w    = t >> 5;
    const int lane = t & 31;

    attn_load_kv(sKV[0][0], sKV[0][1], b, chunk * BK, t);
    asm volatile("cp.async.commit_group;");

    {
        int row = t >> 1, off = (t & 1) * 32;
        const uint4* src = (const uint4*)(g_qh + (size_t)(b * SEQ + q0 + row) * HDIM + off);
        uint4* dst = (uint4*)&sQ[row * STR + off];
        #pragma unroll
        for (int i = 0; i < 4; i++) dst[i] = src[i];
    }
    __syncthreads();

    const int lrow = (lane & 7) + ((lane >> 3) & 1) * 8;
    const int lcol = (lane >> 4) * 8;
    uint32_t qf[4][4];
    #pragma unroll
    for (int kc = 0; kc < 4; kc++)
        ldsm_x4(qf[kc], &sQ[(w * 16 + lrow) * STR + kc * 16 + lcol]);

    float m0 = NEG_BIG, m1 = NEG_BIG, l0 = 0.f, l1 = 0.f;
    float o[8][4];
    #pragma unroll
    for (int j = 0; j < 8; j++)
        #pragma unroll
        for (int e = 0; e < 4; e++) o[j][e] = 0.f;

    int stg = 0;
    for (int kb = chunk; kb < nkb; kb += ct) {
        const int k0 = kb * BK;
        const int nxt = kb + ct;
        if (nxt < nkb) {
            attn_load_kv(sKV[stg ^ 1][0], sKV[stg ^ 1][1], b, nxt * BK, t);
            asm volatile("cp.async.commit_group;");
            asm volatile("cp.async.wait_group 1;");
        } else {
            asm volatile("cp.async.wait_group 0;");
        }
        __syncthreads();

        __half* Kh = sKV[stg][0];
        __half* Vh = sKV[stg][1];

        // ---- S = Q K^T (fp16, fp32 acc; log2 domain via folded q-scale) ----
        float c[8][4];
        #pragma unroll
        for (int j = 0; j < 8; j++)
            #pragma unroll
            for (int e = 0; e < 4; e++) c[j][e] = 0.f;

        #pragma unroll
        for (int kc = 0; kc < 4; kc++) {
            #pragma unroll
            for (int jp = 0; jp < 4; jp++) {
                int krow = 16 * jp + (lane & 7) + (lane >> 4) * 8;
                int kcol = kc * 16 + ((lane >> 3) & 1) * 8;
                uint32_t bh[4];
                ldsm_x4(bh, &Kh[krow * STR + kcol]);
                mma16816(c[2 * jp],     qf[kc], bh[0], bh[1]);
                mma16816(c[2 * jp + 1], qf[kc], bh[2], bh[3]);
            }
        }

        // ---- causal mask ----
        if (k0 + BK - 1 > q0 + w * 16) {
            int r0g = q0 + w * 16 + (lane >> 2);
            #pragma unroll
            for (int j = 0; j < 8; j++) {
                int cgl = k0 + 8 * j + 2 * (lane & 3);
                if (cgl     > r0g)     c[j][0] = NEG_BIG;
                if (cgl + 1 > r0g)     c[j][1] = NEG_BIG;
                if (cgl     > r0g + 8) c[j][2] = NEG_BIG;
                if (cgl + 1 > r0g + 8) c[j][3] = NEG_BIG;
            }
        }

        // ---- online softmax, exp2 domain (fully-masked-block floor) ----
        float mx0 = NEG_BIG, mx1 = NEG_BIG;
        #pragma unroll
        for (int j = 0; j < 8; j++) {
            mx0 = fmaxf(mx0, fmaxf(c[j][0], c[j][1]));
            mx1 = fmaxf(mx1, fmaxf(c[j][2], c[j][3]));
        }
        #pragma unroll
        for (int ox = 1; ox <= 2; ox <<= 1) {
            mx0 = fmaxf(mx0, __shfl_xor_sync(0xffffffffu, mx0, ox));
            mx1 = fmaxf(mx1, __shfl_xor_sync(0xffffffffu, mx1, ox));
        }
        float mn0 = fmaxf(fmaxf(m0, mx0), MFLOOR);
        float mn1 = fmaxf(fmaxf(m1, mx1), MFLOOR);
        float corr0 = ex2(m0 - mn0), corr1 = ex2(m1 - mn1);
        m0 = mn0; m1 = mn1;

        float rs0 = 0.f, rs1 = 0.f;
        uint32_t ap[4][4];
        #pragma unroll
        for (int j = 0; j < 8; j++) {
            float p00 = ex2(c[j][0] - mn0);
            float p01 = ex2(c[j][1] - mn0);
            float p10 = ex2(c[j][2] - mn1);
            float p11 = ex2(c[j][3] - mn1);
            rs0 += p00 + p01;
            rs1 += p10 + p11;
            int kc2 = j >> 1, sel = (j & 1) * 2;
            ap[kc2][sel + 0] = packh2(p00, p01);
            ap[kc2][sel + 1] = packh2(p10, p11);
        }
        #pragma unroll
        for (int ox = 1; ox <= 2; ox <<= 1) {
            rs0 += __shfl_xor_sync(0xffffffffu, rs0, ox);
            rs1 += __shfl_xor_sync(0xffffffffu, rs1, ox);
        }
        l0 = l0 * corr0 + rs0;
        l1 = l1 * corr1 + rs1;
        #pragma unroll
        for (int j = 0; j < 8; j++) {
            o[j][0] *= corr0; o[j][1] *= corr0;
            o[j][2] *= corr1; o[j][3] *= corr1;
        }

        // ---- O += P V (fp16) ----
        #pragma unroll
        for (int kc2 = 0; kc2 < 4; kc2++) {
            #pragma unroll
            for (int up = 0; up < 4; up++) {
                int vrow = 16 * kc2 + (lane & 7) + ((lane >> 3) & 1) * 8;
                int vcol = 16 * up + (lane >> 4) * 8;
                uint32_t bv[4];
                ldsm_x4_t(bv, &Vh[vrow * STR + vcol]);
                mma16816(o[2 * up],     ap[kc2], bv[0], bv[1]);
                mma16816(o[2 * up + 1], ap[kc2], bv[2], bv[3]);
            }
        }

        __syncthreads();
        stg ^= 1;
    }

    // ---- write partials ----
    int rl0 = b * SEQ + q0 + w * 16 + (lane >> 2);
    if ((lane & 3) == 0) {
        g_pm[chunk][rl0]     = m0;  g_pl[chunk][rl0]     = l0;
        g_pm[chunk][rl0 + 8] = m1;  g_pl[chunk][rl0 + 8] = l1;
    }
    #pragma unroll
    for (int j = 0; j < 8; j++) {
        int col = 8 * j + 2 * (lane & 3);
        *(float2*)&g_po[chunk][(size_t)rl0 * HDIM + col]       = make_float2(o[j][0], o[j][1]);
        *(float2*)&g_po[chunk][(size_t)(rl0 + 8) * HDIM + col] = make_float2(o[j][2], o[j][3]);
    }

    // ---- fused combine: last CTA of this (b, tile) reduces ct partials ----
    __syncthreads();
    if (t == 0) {
        __threadfence();
        int done = atomicAdd(&g_cnt[b * 16 + tile], 1);
        s_last = (done == ct - 1);
        if (s_last) __threadfence();
    }
    __syncthreads();

    if (s_last) {
        #pragma unroll
        for (int i = 0; i < 8; i++) {
            int idx = t + i * 256;            // 0..2047 over 128 rows x 16 f4
            int row = b * SEQ + q0 + (idx >> 4);
            int col = (idx & 15) * 4;

            float mx = NEG_BIG;
            for (int cI = 0; cI < ct; cI++) mx = fmaxf(mx, g_pm[cI][row]);

            float l = 0.f;
            float4 acc = make_float4(0.f, 0.f, 0.f, 0.f);
            for (int cI = 0; cI < ct; cI++) {
                float s = ex2(g_pm[cI][row] - mx);
                l += s * g_pl[cI][row];
                float4 p = *(const float4*)&g_po[cI][(size_t)row * HDIM + col];
                acc.x += s * p.x;  acc.y += s * p.y;
                acc.z += s * p.z;  acc.w += s * p.w;
            }
            float inv = 1.0f / l;
            acc.x *= inv; acc.y *= inv; acc.z *= inv; acc.w *= inv;
            *(float4*)&out[(size_t)row * HDIM + col] = acc;
        }
    }
}

// ---------------------------------------------------------------------------
extern "C" void kernel_launch(void* const* d_in, const int* in_sizes, int n_in,
                              void* d_out, int out_size)
{
    const float* x  = (const float*)d_in[0];
    const float* Wk = (const float*)d_in[1];
    const float* Wq = (const float*)d_in[2];
    const float* Wv = (const float*)d_in[3];
    float* out = (float*)d_out;

    const int gsmem = 2 * STGB;   // 204800 B
    cudaFuncSetAttribute(qkv_gemm_mma, cudaFuncAttributeMaxDynamicSharedMemorySize, gsmem);
    qkv_gemm_mma<<<ROWS / BM, 256, gsmem>>>(x, Wk, Wq, Wv);

    const int asmem = (BQ * STR + 4 * BK * STR) * (int)sizeof(__half);  // 55296
    cudaFuncSetAttribute(attn_kernel, cudaFuncAttributeMaxDynamicSharedMemorySize, asmem);
    dim3 agrid(CTAS_PER_B, BATCH);
    attn_kernel<<<agrid, 256, asmem>>>(out);
}

// round 17
// speedup vs baseline: 1.2315x; 1.2315x over previous
#include <cuda_runtime.h>
#include <cuda_fp16.h>
#include <cstdint>

// B=4, T=2048, E=768, H=64 — causal single-head attention, fp32 out.
//  K1 qkv_gemm_mma: tf32 m16n8k8 GEMM, Q-scale*log2e folded (R15 config).
//  K2 attn_kernel: fp16 flash attention, BQ=128, split-K 4, ex2 softmax,
//     fused last-CTA combine. NEW: bid->work permutation pairs heavy tiles
//     with light tiles on the same SM (bid i co-resides with bid i+148).

#define BATCH 4
#define SEQ   2048
#define EMB   768
#define HDIM  64
#define ROWS  (BATCH*SEQ)   // 8192
#define NCHUNK 4
#define LOG2E 1.4426950408889634f

__device__ __half g_qh[ROWS*HDIM], g_kh[ROWS*HDIM], g_vh[ROWS*HDIM];
__device__ float g_pm[NCHUNK][ROWS], g_pl[NCHUNK][ROWS], g_po[NCHUNK][ROWS*HDIM];
__device__ int   g_cnt[64];                                       // [b][tile]

// ---------------- helpers (sm_80+ baseline PTX) ------------------------------
__device__ __forceinline__ void ldsm_x4(uint32_t* r, const void* p) {
    uint32_t a = (uint32_t)__cvta_generic_to_shared(p);
    asm volatile("ldmatrix.sync.aligned.m8n8.x4.shared.b16 {%0,%1,%2,%3}, [%4];"
                 : "=r"(r[0]), "=r"(r[1]), "=r"(r[2]), "=r"(r[3]) : "r"(a));
}
__device__ __forceinline__ void ldsm_x4_t(uint32_t* r, const void* p) {
    uint32_t a = (uint32_t)__cvta_generic_to_shared(p);
    asm volatile("ldmatrix.sync.aligned.m8n8.x4.trans.shared.b16 {%0,%1,%2,%3}, [%4];"
                 : "=r"(r[0]), "=r"(r[1]), "=r"(r[2]), "=r"(r[3]) : "r"(a));
}
__device__ __forceinline__ void mma16816(float* c, const uint32_t* a,
                                         uint32_t b0, uint32_t b1) {
    asm volatile("mma.sync.aligned.m16n8k16.row.col.f32.f16.f16.f32 "
                 "{%0,%1,%2,%3}, {%4,%5,%6,%7}, {%8,%9}, {%0,%1,%2,%3};"
                 : "+f"(c[0]), "+f"(c[1]), "+f"(c[2]), "+f"(c[3])
                 : "r"(a[0]), "r"(a[1]), "r"(a[2]), "r"(a[3]), "r"(b0), "r"(b1));
}
__device__ __forceinline__ void mma16888(float* c,
                                         uint32_t a0, uint32_t a1, uint32_t a2, uint32_t a3,
                                         uint32_t b0, uint32_t b1) {
    asm volatile("mma.sync.aligned.m16n8k8.row.col.f32.tf32.tf32.f32 "
                 "{%0,%1,%2,%3}, {%4,%5,%6,%7}, {%8,%9}, {%0,%1,%2,%3};"
                 : "+f"(c[0]), "+f"(c[1]), "+f"(c[2]), "+f"(c[3])
                 : "r"(a0), "r"(a1), "r"(a2), "r"(a3), "r"(b0), "r"(b1));
}
__device__ __forceinline__ uint32_t cvt_tf32(float s) {
    uint32_t d;
    asm("cvt.rna.tf32.f32 %0, %1;" : "=r"(d) : "f"(s));
    return d;
}
__device__ __forceinline__ float ex2(float x) {
    float y;
    asm("ex2.approx.f32 %0, %1;" : "=f"(y) : "f"(x));
    return y;
}
__device__ __forceinline__ uint32_t packh2(float a, float b) {
    __half2 h = __floats2half2_rn(a, b);
    return *reinterpret_cast<uint32_t*>(&h);
}
__device__ __forceinline__ void cp16(void* dst, const void* src) {
    uint32_t d = (uint32_t)__cvta_generic_to_shared(dst);
    asm volatile("cp.async.cg.shared.global [%0], [%1], 16;" :: "r"(d), "l"(src));
}

extern __shared__ char smbase[];

#define NEG_BIG (-1e30f)
#define MFLOOR  (-1e28f)

// ---------------------------------------------------------------------------
// K1: fused QKV GEMM on tf32 (unchanged from R15). CTA = 64x192, 8 warps,
// warp tile 32x48 via m16n8k8, BKC=96, 2-stage cp.async.
// ---------------------------------------------------------------------------
#define BM    64
#define BKC   96
#define XSTRF 100
#define WSTR  200
#define STGB  (BM*XSTRF*4 + BKC*WSTR*4)   // 102400

__device__ __forceinline__ void gemm_load_stage(char* st, const float* x,
                                                const float* Wq, const float* Wk,
                                                const float* Wv, int m0, int kc0, int t)
{
    float* Xf = (float*)st;
    float* Wf = (float*)(st + BM * XSTRF * 4);

    {
        int row = t >> 2, coff = (t & 3) * 24;
        const float* sx = x + (size_t)(m0 + row) * EMB + kc0 + coff;
        #pragma unroll
        for (int i = 0; i < 6; i++)
            cp16(&Xf[row * XSTRF + coff + i * 4], sx + i * 4);
    }
    #pragma unroll
    for (int i = 0; i < 18; i++) {
        int idx = t + i * 256;
        int wr = idx / 48, c = idx % 48;
        const float* Warr = (c < 16) ? Wq : (c < 32) ? Wk : Wv;
        int wc = (c & 15) * 4;
        cp16(&Wf[wr * WSTR + c * 4], Warr + (size_t)(kc0 + wr) * HDIM + wc);
    }
}

__global__ __launch_bounds__(256)
void qkv_gemm_mma(const float* __restrict__ x,
                  const float* __restrict__ Wk,
                  const float* __restrict__ Wq,
                  const float* __restrict__ Wv)
{
    if (blockIdx.x == 0 && threadIdx.x < 64) g_cnt[threadIdx.x] = 0;

    const int m0   = blockIdx.x * BM;
    const int t    = threadIdx.x;
    const int w    = t >> 5;
    const int lane = t & 31;
    const int rg   = w >> 2;
    const int cg   = w & 3;
    const int gid  = lane >> 2;
    const int tid  = lane & 3;

    const float qsc = rsqrtf((float)EMB) * LOG2E;

    float c[2][6][4];
    #pragma unroll
    for (int mt = 0; mt < 2; mt++)
        #pragma unroll
        for (int j = 0; j < 6; j++)
            #pragma unroll
            for (int e = 0; e < 4; e++) c[mt][j][e] = 0.f;

    const int NC = EMB / BKC;   // 8

    gemm_load_stage(smbase, x, Wq, Wk, Wv, m0, 0, t);
    asm volatile("cp.async.commit_group;");

    for (int kc = 0; kc < NC; kc++) {
        if (kc + 1 < NC) {
            gemm_load_stage(smbase + ((kc + 1) & 1) * STGB, x, Wq, Wk, Wv,
                            m0, (kc + 1) * BKC, t);
            asm volatile("cp.async.commit_group;");
            asm volatile("cp.async.wait_group 1;");
        } else {
            asm volatile("cp.async.wait_group 0;");
        }
        __syncthreads();

        char*  st = smbase + (kc & 1) * STGB;
        float* Xf = (float*)st;
        float* Wf = (float*)(st + BM * XSTRF * 4);

        #pragma unroll
        for (int kt = 0; kt < BKC / 8; kt++) {
            uint32_t a[2][4];
            #pragma unroll
            for (int mt = 0; mt < 2; mt++) {
                const float* ab = &Xf[(rg * 32 + mt * 16 + gid) * XSTRF + kt * 8 + tid];
                a[mt][0] = cvt_tf32(ab[0]);
                a[mt][1] = cvt_tf32(ab[8 * XSTRF]);
                a[mt][2] = cvt_tf32(ab[4]);
                a[mt][3] = cvt_tf32(ab[8 * XSTRF + 4]);
            }
            #pragma unroll
            for (int nt = 0; nt < 6; nt++) {
                const float sc = (cg * 48 + nt * 8 < 64) ? qsc : 1.0f;
                const float* bb = &Wf[(kt * 8 + tid) * WSTR + cg * 48 + nt * 8 + gid];
                uint32_t b0 = cvt_tf32(bb[0] * sc);
                uint32_t b1 = cvt_tf32(bb[4 * WSTR] * sc);
                mma16888(c[0][nt], a[0][0], a[0][1], a[0][2], a[0][3], b0, b1);
                mma16888(c[1][nt], a[1][0], a[1][1], a[1][2], a[1][3], b0, b1);
            }
        }
        __syncthreads();
    }

    #pragma unroll
    for (int mt = 0; mt < 2; mt++) {
        int r0 = m0 + rg * 32 + mt * 16 + gid;
        #pragma unroll
        for (int j = 0; j < 6; j++) {
            int col_local = cg * 48 + j * 8 + 2 * tid;
            int widx = col_local >> 6;
            int col  = col_local & 63;
            __half* oh = (widx == 0) ? g_qh : (widx == 1) ? g_kh : g_vh;
            *(uint32_t*)&oh[(size_t)r0 * HDIM + col]       = packh2(c[mt][j][0], c[mt][j][1]);
            *(uint32_t*)&oh[(size_t)(r0 + 8) * HDIM + col] = packh2(c[mt][j][2], c[mt][j][3]);
        }
    }
}

// ---------------------------------------------------------------------------
// K2: fp16 flash attention (R15 config) with balanced bid->work permutation:
// eid = (bid < 148) ? bid : 403 - bid; SM hosting bids i and i+148 gets items
// i and 255-i -> pair sums ~constant. BQ=128, split-K 4, cp.async double
// buffer, ex2 softmax, fused last-CTA combine.
// smem: sQ[128*72] + stages[2][K,V][64*72] halves = 55296 B dynamic.
// ---------------------------------------------------------------------------
#define BQ   128
#define BK   64
#define STR  72

__device__ __forceinline__ void attn_load_kv(__half* Kh, __half* Vh,
                                             int b, int k0, int t)
{
    int row = t >> 2, off = (t & 3) * 16;
    const __half* sk = g_kh + (size_t)(b * SEQ + k0 + row) * HDIM + off;
    const __half* sv = g_vh + (size_t)(b * SEQ + k0 + row) * HDIM + off;
    cp16(&Kh[row * STR + off],     sk);
    cp16(&Kh[row * STR + off + 8], sk + 8);
    cp16(&Vh[row * STR + off],     sv);
    cp16(&Vh[row * STR + off + 8], sv + 8);
}

__global__ __launch_bounds__(256, 2)
void attn_kernel(float* __restrict__ out)
{
    __half* sQ = (__half*)smbase;                     // 9216 halves
    __half* sKV[2][2];
    #pragma unroll
    for (int s = 0; s < 2; s++)
        #pragma unroll
        for (int kv = 0; kv < 2; kv++)
            sKV[s][kv] = (__half*)smbase + BQ * STR + (s * 2 + kv) * BK * STR;

    __shared__ int s_last;

    // ---- balanced bid->work permutation ----
    const int bid  = blockIdx.x;                 // 0..255
    const int eid  = (bid < 148) ? bid : 403 - bid;
    const int b    = eid >> 6;                   // 0..3
    const int xw   = eid & 63;
    const int tile = xw >> 2;                    // 0..15
    const int chunk= xw & 3;

    const int q0   = tile * BQ;
    const int t    = threadIdx.x;
    const int w    = t >> 5;
    const int lane = t & 31;

    const int nkb = 2 * tile + 2;
    const bool has_work = (chunk < nkb);

    if (has_work) attn_load_kv(sKV[0][0], sKV[0][1], b, chunk * BK, t);
    asm volatile("cp.async.commit_group;");

    {
        int row = t >> 1, off = (t & 1) * 32;
        const uint4* src = (const uint4*)(g_qh + (size_t)(b * SEQ + q0 + row) * HDIM + off);
        uint4* dst = (uint4*)&sQ[row * STR + off];
        #pragma unroll
        for (int i = 0; i < 4; i++) dst[i] = src[i];
    }
    __syncthreads();

    const int lrow = (lane & 7) + ((lane >> 3) & 1) * 8;
    const int lcol = (lane >> 4) * 8;
    uint32_t qf[4][4];
    #pragma unroll
    for (int kc = 0; kc < 4; kc++)
        ldsm_x4(qf[kc], &sQ[(w * 16 + lrow) * STR + kc * 16 + lcol]);

    float m0 = NEG_BIG, m1 = NEG_BIG, l0 = 0.f, l1 = 0.f;
    float o[8][4];
    #pragma unroll
    for (int j = 0; j < 8; j++)
        #pragma unroll
        for (int e = 0; e < 4; e++) o[j][e] = 0.f;

    int stg = 0;
    for (int kb = chunk; kb < nkb; kb += NCHUNK) {
        const int k0 = kb * BK;
        const int nxt = kb + NCHUNK;
        if (nxt < nkb) {
            attn_load_kv(sKV[stg ^ 1][0], sKV[stg ^ 1][1], b, nxt * BK, t);
            asm volatile("cp.async.commit_group;");
            asm volatile("cp.async.wait_group 1;");
        } else {
            asm volatile("cp.async.wait_group 0;");
        }
        __syncthreads();

        __half* Kh = sKV[stg][0];
        __half* Vh = sKV[stg][1];

        // ---- S = Q K^T (fp16, fp32 acc; log2 domain via folded q-scale) ----
        float c[8][4];
        #pragma unroll
        for (int j = 0; j < 8; j++)
            #pragma unroll
            for (int e = 0; e < 4; e++) c[j][e] = 0.f;

        #pragma unroll
        for (int kc = 0; kc < 4; kc++) {
            #pragma unroll
            for (int jp = 0; jp < 4; jp++) {
                int krow = 16 * jp + (lane & 7) + (lane >> 4) * 8;
                int kcol = kc * 16 + ((lane >> 3) & 1) * 8;
                uint32_t bh[4];
                ldsm_x4(bh, &Kh[krow * STR + kcol]);
                mma16816(c[2 * jp],     qf[kc], bh[0], bh[1]);
                mma16816(c[2 * jp + 1], qf[kc], bh[2], bh[3]);
            }
        }

        // ---- causal mask ----
        if (k0 + BK - 1 > q0 + w * 16) {
            int r0g = q0 + w * 16 + (lane >> 2);
            #pragma unroll
            for (int j = 0; j < 8; j++) {
                int cgl = k0 + 8 * j + 2 * (lane & 3);
                if (cgl     > r0g)     c[j][0] = NEG_BIG;
                if (cgl + 1 > r0g)     c[j][1] = NEG_BIG;
                if (cgl     > r0g + 8) c[j][2] = NEG_BIG;
                if (cgl + 1 > r0g + 8) c[j][3] = NEG_BIG;
            }
        }

        // ---- online softmax, exp2 domain (fully-masked-block floor) ----
        float mx0 = NEG_BIG, mx1 = NEG_BIG;
        #pragma unroll
        for (int j = 0; j < 8; j++) {
            mx0 = fmaxf(mx0, fmaxf(c[j][0], c[j][1]));
            mx1 = fmaxf(mx1, fmaxf(c[j][2], c[j][3]));
        }
        #pragma unroll
        for (int ox = 1; ox <= 2; ox <<= 1) {
            mx0 = fmaxf(mx0, __shfl_xor_sync(0xffffffffu, mx0, ox));
            mx1 = fmaxf(mx1, __shfl_xor_sync(0xffffffffu, mx1, ox));
        }
        float mn0 = fmaxf(fmaxf(m0, mx0), MFLOOR);
        float mn1 = fmaxf(fmaxf(m1, mx1), MFLOOR);
        float corr0 = ex2(m0 - mn0), corr1 = ex2(m1 - mn1);
        m0 = mn0; m1 = mn1;

        float rs0 = 0.f, rs1 = 0.f;
        uint32_t ap[4][4];
        #pragma unroll
        for (int j = 0; j < 8; j++) {
            float p00 = ex2(c[j][0] - mn0);
            float p01 = ex2(c[j][1] - mn0);
            float p10 = ex2(c[j][2] - mn1);
            float p11 = ex2(c[j][3] - mn1);
            rs0 += p00 + p01;
            rs1 += p10 + p11;
            int kc2 = j >> 1, sel = (j & 1) * 2;
            ap[kc2][sel + 0] = packh2(p00, p01);
            ap[kc2][sel + 1] = packh2(p10, p11);
        }
        #pragma unroll
        for (int ox = 1; ox <= 2; ox <<= 1) {
            rs0 += __shfl_xor_sync(0xffffffffu, rs0, ox);
            rs1 += __shfl_xor_sync(0xffffffffu, rs1, ox);
        }
        l0 = l0 * corr0 + rs0;
        l1 = l1 * corr1 + rs1;
        #pragma unroll
        for (int j = 0; j < 8; j++) {
            o[j][0] *= corr0; o[j][1] *= corr0;
            o[j][2] *= corr1; o[j][3] *= corr1;
        }

        // ---- O += P V (fp16) ----
        #pragma unroll
        for (int kc2 = 0; kc2 < 4; kc2++) {
            #pragma unroll
            for (int up = 0; up < 4; up++) {
                int vrow = 16 * kc2 + (lane & 7) + ((lane >> 3) & 1) * 8;
                int vcol = 16 * up + (lane >> 4) * 8;
                uint32_t bv[4];
                ldsm_x4_t(bv, &Vh[vrow * STR + vcol]);
                mma16816(o[2 * up],     ap[kc2], bv[0], bv[1]);
                mma16816(o[2 * up + 1], ap[kc2], bv[2], bv[3]);
            }
        }

        __syncthreads();
        stg ^= 1;
    }

    // ---- write partials ----
    int rl0 = b * SEQ + q0 + w * 16 + (lane >> 2);
    if ((lane & 3) == 0) {
        g_pm[chunk][rl0]     = m0;  g_pl[chunk][rl0]     = l0;
        g_pm[chunk][rl0 + 8] = m1;  g_pl[chunk][rl0 + 8] = l1;
    }
    #pragma unroll
    for (int j = 0; j < 8; j++) {
        int col = 8 * j + 2 * (lane & 3);
        *(float2*)&g_po[chunk][(size_t)rl0 * HDIM + col]       = make_float2(o[j][0], o[j][1]);
        *(float2*)&g_po[chunk][(size_t)(rl0 + 8) * HDIM + col] = make_float2(o[j][2], o[j][3]);
    }

    // ---- fused combine: last CTA of this (b, tile) reduces all 4 partials ----
    __syncthreads();
    if (t == 0) {
        __threadfence();
        int done = atomicAdd(&g_cnt[b * 16 + tile], 1);
        s_last = (done == NCHUNK - 1);
        if (s_last) __threadfence();
    }
    __syncthreads();

    if (s_last) {
        #pragma unroll
        for (int i = 0; i < 8; i++) {
            int idx = t + i * 256;            // 0..2047 over 128 rows x 16 f4
            int row = b * SEQ + q0 + (idx >> 4);
            int col = (idx & 15) * 4;

            float mx = NEG_BIG;
            #pragma unroll
            for (int cI = 0; cI < NCHUNK; cI++) mx = fmaxf(mx, g_pm[cI][row]);

            float l = 0.f;
            float4 acc = make_float4(0.f, 0.f, 0.f, 0.f);
            #pragma unroll
            for (int cI = 0; cI < NCHUNK; cI++) {
                float s = ex2(g_pm[cI][row] - mx);
                l += s * g_pl[cI][row];
                float4 p = *(const float4*)&g_po[cI][(size_t)row * HDIM + col];
                acc.x += s * p.x;  acc.y += s * p.y;
                acc.z += s * p.z;  acc.w += s * p.w;
            }
            float inv = 1.0f / l;
            acc.x *= inv; acc.y *= inv; acc.z *= inv; acc.w *= inv;
            *(float4*)&out[(size_t)row * HDIM + col] = acc;
        }
    }
}

// ---------------------------------------------------------------------------
extern "C" void kernel_launch(void* const* d_in, const int* in_sizes, int n_in,
                              void* d_out, int out_size)
{
    const float* x  = (const float*)d_in[0];
    const float* Wk = (const float*)d_in[1];
    const float* Wq = (const float*)d_in[2];
    const float* Wv = (const float*)d_in[3];
    float* out = (float*)d_out;

    const int gsmem = 2 * STGB;   // 204800 B
    cudaFuncSetAttribute(qkv_gemm_mma, cudaFuncAttributeMaxDynamicSharedMemorySize, gsmem);
    qkv_gemm_mma<<<ROWS / BM, 256, gsmem>>>(x, Wk, Wq, Wv);

    const int asmem = (BQ * STR + 4 * BK * STR) * (int)sizeof(__half);  // 55296
    cudaFuncSetAttribute(attn_kernel, cudaFuncAttributeMaxDynamicSharedMemorySize, asmem);
    attn_kernel<<<256, 256, asmem>>>(out);
}